// round 4
// baseline (speedup 1.0000x reference)
#include <cuda_runtime.h>
#include <math.h>
#include <stdint.h>

#define NN 50000
#define EE 400000
#define ET 450000      // EE + NN self loops
#define LN_EPS 1e-5f

// ---------------- scratch (device globals; allocation is forbidden) ----------
__device__ float g_h[(size_t)NN * 512];     // GEMM output per layer
__device__ float g_feat[(size_t)NN * 512];  // layer output / next input
__device__ float g_ssrc[NN * 4];
__device__ float g_sdst[NN * 4];
__device__ int   g_cnt[NN];                 // per-dst real-edge count
__device__ int   g_off[NN + 1];             // CSR offsets (incl. self loops)
__device__ int   g_pos[NN];                 // scatter cursors
__device__ int   g_srcs[ET];                // src node per CSR slot

// ---------------- 3xTF32 tensor-core GEMM ------------------------------------
// C[M,N] = A[M,K] @ B[K,N], all row-major fp32.
// Block tile 128x64, BK=16, 256 threads (8 warps, 4x2), warp tile 32x32.
// Split hi/lo in tf32; acc += Ah*Bh + Ah*Bl + Al*Bh (~fp32 accuracy).

__device__ __forceinline__ uint32_t f2tf32(float x) {
    uint32_t r;
    asm("cvt.rna.tf32.f32 %0, %1;" : "=r"(r) : "f"(x));
    return r;
}

__device__ __forceinline__ void mma_tf32(float* c, const float* a, const float* b) {
    asm volatile(
        "mma.sync.aligned.m16n8k8.row.col.f32.tf32.tf32.f32 "
        "{%0,%1,%2,%3}, {%4,%5,%6,%7}, {%8,%9}, {%0,%1,%2,%3};"
        : "+f"(c[0]), "+f"(c[1]), "+f"(c[2]), "+f"(c[3])
        : "r"(__float_as_uint(a[0])), "r"(__float_as_uint(a[1])),
          "r"(__float_as_uint(a[2])), "r"(__float_as_uint(a[3])),
          "r"(__float_as_uint(b[0])), "r"(__float_as_uint(b[1])));
}

__global__ __launch_bounds__(256) void gemm_tf32(
        const float* __restrict__ A, const float* __restrict__ B,
        float* __restrict__ C, int M, int N, int K) {
    __shared__ float Ah[16][136], Al[16][136];
    __shared__ float Bh[16][72],  Bl[16][72];

    int tid = threadIdx.x;
    int lane = tid & 31, wid = tid >> 5;
    int wm = (wid >> 1) * 32;
    int wn = (wid & 1) * 32;
    int q = lane & 3, t4 = lane >> 2;
    int row0 = blockIdx.y * 128, col0 = blockIdx.x * 64;

    float acc[2][4][4];
#pragma unroll
    for (int i = 0; i < 2; i++)
#pragma unroll
        for (int j = 0; j < 4; j++)
#pragma unroll
            for (int k = 0; k < 4; k++) acc[i][j][k] = 0.f;

    for (int k0 = 0; k0 < K; k0 += 16) {
#pragma unroll
        for (int i = 0; i < 2; i++) {
            int j = tid + 256 * i;
            int r = j >> 2, c = (j & 3) << 2;
            float4 v;
            if (row0 + r < M) v = *(const float4*)(A + (size_t)(row0 + r) * K + k0 + c);
            else              v = make_float4(0.f, 0.f, 0.f, 0.f);
            float vv[4] = {v.x, v.y, v.z, v.w};
#pragma unroll
            for (int t = 0; t < 4; t++) {
                uint32_t hb = f2tf32(vv[t]);
                float hf = __uint_as_float(hb);
                Ah[c + t][r] = hf;
                Al[c + t][r] = __uint_as_float(f2tf32(vv[t] - hf));
            }
        }
        {
            int r = tid >> 4, c = (tid & 15) << 2;
            float4 v = *(const float4*)(B + (size_t)(k0 + r) * N + col0 + c);
            float vv[4] = {v.x, v.y, v.z, v.w};
            float4 h4, l4;
            float* hp = &h4.x; float* lp = &l4.x;
#pragma unroll
            for (int t = 0; t < 4; t++) {
                uint32_t hb = f2tf32(vv[t]);
                float hf = __uint_as_float(hb);
                hp[t] = hf;
                lp[t] = __uint_as_float(f2tf32(vv[t] - hf));
            }
            *(float4*)(&Bh[r][c]) = h4;
            *(float4*)(&Bl[r][c]) = l4;
        }
        __syncthreads();

#pragma unroll
        for (int kk = 0; kk < 16; kk += 8) {
            float ah[2][4], al[2][4], bh[4][2], bl[4][2];
#pragma unroll
            for (int mt = 0; mt < 2; mt++) {
                int m0 = wm + mt * 16 + t4;
                ah[mt][0] = Ah[kk + q][m0];     ah[mt][1] = Ah[kk + q][m0 + 8];
                ah[mt][2] = Ah[kk + q + 4][m0]; ah[mt][3] = Ah[kk + q + 4][m0 + 8];
                al[mt][0] = Al[kk + q][m0];     al[mt][1] = Al[kk + q][m0 + 8];
                al[mt][2] = Al[kk + q + 4][m0]; al[mt][3] = Al[kk + q + 4][m0 + 8];
            }
#pragma unroll
            for (int nt = 0; nt < 4; nt++) {
                int n0 = wn + nt * 8 + t4;
                bh[nt][0] = Bh[kk + q][n0]; bh[nt][1] = Bh[kk + q + 4][n0];
                bl[nt][0] = Bl[kk + q][n0]; bl[nt][1] = Bl[kk + q + 4][n0];
            }
#pragma unroll
            for (int mt = 0; mt < 2; mt++)
#pragma unroll
                for (int nt = 0; nt < 4; nt++) {
                    mma_tf32(acc[mt][nt], ah[mt], bh[nt]);
                    mma_tf32(acc[mt][nt], ah[mt], bl[nt]);
                    mma_tf32(acc[mt][nt], al[mt], bh[nt]);
                }
        }
        __syncthreads();
    }

#pragma unroll
    for (int mt = 0; mt < 2; mt++) {
        int r0 = row0 + wm + mt * 16 + t4;
#pragma unroll
        for (int nt = 0; nt < 4; nt++) {
            int cc = col0 + wn + nt * 8 + q * 2;
            if (r0 < M) {
                C[(size_t)r0 * N + cc]     = acc[mt][nt][0];
                C[(size_t)r0 * N + cc + 1] = acc[mt][nt][1];
            }
            if (r0 + 8 < M) {
                C[(size_t)(r0 + 8) * N + cc]     = acc[mt][nt][2];
                C[(size_t)(r0 + 8) * N + cc + 1] = acc[mt][nt][3];
            }
        }
    }
}

// ---------------- CSR construction -------------------------------------------
__global__ void zero_k(int* __restrict__ cnt, int* __restrict__ pos) {
    int i = blockIdx.x * blockDim.x + threadIdx.x;
    if (i < NN) { cnt[i] = 0; pos[i] = 0; }
}

__global__ void hist_k(const int* __restrict__ ei, int* __restrict__ cnt) {
    int e = blockIdx.x * blockDim.x + threadIdx.x;
    if (e < EE) atomicAdd(&cnt[ei[EE + e]], 1);
}

// single-block inclusive scan of (cnt[i]+1) -> off[i+1]; off[0]=0
__global__ void scan_k(const int* __restrict__ cnt, int* __restrict__ off) {
    __shared__ int sh[1024];
    __shared__ int carry;
    int t = threadIdx.x;
    if (t == 0) carry = 0;
    __syncthreads();
    for (int base = 0; base < NN; base += 1024) {
        int i = base + t;
        int v = (i < NN) ? cnt[i] + 1 : 0;
        sh[t] = v;
        __syncthreads();
        for (int o = 1; o < 1024; o <<= 1) {
            int add = (t >= o) ? sh[t - o] : 0;
            __syncthreads();
            sh[t] += add;
            __syncthreads();
        }
        int total = sh[1023];
        if (i < NN) off[i + 1] = carry + sh[t];
        __syncthreads();
        if (t == 0) carry += total;
        __syncthreads();
    }
    if (t == 0) off[0] = 0;
}

__global__ void scatter_k(const int* __restrict__ ei, const int* __restrict__ off,
                          int* __restrict__ pos, int* __restrict__ srcs) {
    int e = blockIdx.x * blockDim.x + threadIdx.x;
    if (e >= ET) return;
    int s, d;
    if (e < EE) { s = ei[e]; d = ei[EE + e]; }
    else        { s = e - EE; d = s; }
    int p = atomicAdd(&pos[d], 1);
    srcs[off[d] + p] = s;
}

// ---------------- per-node attention scores: s = <h[n,h,:], a[h,:]> ----------
__global__ void scores_k(const float* __restrict__ h, const float* __restrict__ asrc,
                         const float* __restrict__ adst, float* __restrict__ ssrc,
                         float* __restrict__ sdst, int H, int C) {
    int warp = (blockIdx.x * blockDim.x + threadIdx.x) >> 5;
    int lane = threadIdx.x & 31;
    if (warp >= NN) return;
    int HC = H * C;
    for (int hd = 0; hd < H; hd++) {
        float ps = 0.f, pd = 0.f;
        for (int c = lane * 4; c < C; c += 128) {
            float4 hv = *(const float4*)(h + (size_t)warp * HC + hd * C + c);
            float4 as = *(const float4*)(asrc + hd * C + c);
            float4 ad = *(const float4*)(adst + hd * C + c);
            ps += hv.x * as.x + hv.y * as.y + hv.z * as.z + hv.w * as.w;
            pd += hv.x * ad.x + hv.y * ad.y + hv.z * ad.z + hv.w * ad.w;
        }
#pragma unroll
        for (int o = 16; o; o >>= 1) {
            ps += __shfl_down_sync(0xffffffffu, ps, o);
            pd += __shfl_down_sync(0xffffffffu, pd, o);
        }
        if (lane == 0) { ssrc[warp * H + hd] = ps; sdst[warp * H + hd] = pd; }
    }
}

// ---------------- fused GAT tail: softmax + aggregate + bias + LN + ELU ------
// One block (128 threads) per dst node. No atomics, each output written once.
#define CHUNK 64
__global__ __launch_bounds__(128) void gat_agg_k(
        const int* __restrict__ off, const int* __restrict__ srcs,
        const float* __restrict__ h, const float* __restrict__ ssrc,
        const float* __restrict__ sdst, const float* __restrict__ bias,
        const float* __restrict__ lng, const float* __restrict__ lnb,
        float* __restrict__ out, int H, int HC, int shiftC) {
    __shared__ float s_m[4], s_den[4];
    __shared__ float s_alpha[CHUNK][4];
    __shared__ int   s_src[CHUNK];
    __shared__ float red[256];

    int n = blockIdx.x;
    int t = threadIdx.x;
    int beg = off[n], end = off[n + 1];

    // phase A: per-head max and exp-sum over incoming edges (warp 0)
    if (t < 32) {
        float mx[4] = {-INFINITY, -INFINITY, -INFINITY, -INFINITY};
        float dn[4] = {0.f, 0.f, 0.f, 0.f};
        for (int j = beg + t; j < end; j += 32) {
            int s = srcs[j];
            for (int hd = 0; hd < H; hd++) {
                float v = ssrc[s * H + hd] + sdst[n * H + hd];
                v = v > 0.f ? v : 0.2f * v;
                mx[hd] = fmaxf(mx[hd], v);
            }
        }
#pragma unroll
        for (int o = 16; o; o >>= 1)
            for (int hd = 0; hd < H; hd++)
                mx[hd] = fmaxf(mx[hd], __shfl_xor_sync(0xffffffffu, mx[hd], o));
        for (int j = beg + t; j < end; j += 32) {
            int s = srcs[j];
            for (int hd = 0; hd < H; hd++) {
                float v = ssrc[s * H + hd] + sdst[n * H + hd];
                v = v > 0.f ? v : 0.2f * v;
                dn[hd] += expf(v - mx[hd]);
            }
        }
#pragma unroll
        for (int o = 16; o; o >>= 1)
            for (int hd = 0; hd < H; hd++)
                dn[hd] += __shfl_xor_sync(0xffffffffu, dn[hd], o);
        if (t == 0)
            for (int hd = 0; hd < H; hd++) { s_m[hd] = mx[hd]; s_den[hd] = dn[hd]; }
    }
    __syncthreads();

    // phase B: aggregate. thread t owns channels [t*4, t*4+4)
    int c0 = t * 4;
    bool act = c0 < HC;
    int hd0 = act ? (c0 >> shiftC) : 0;
    float4 acc = make_float4(0.f, 0.f, 0.f, 0.f);

    for (int cb = beg; cb < end; cb += CHUNK) {
        int clen = min(CHUNK, end - cb);
        __syncthreads();
        if (t < clen) {
            int s = srcs[cb + t];
            s_src[t] = s;
            for (int hd = 0; hd < H; hd++) {
                float v = ssrc[s * H + hd] + sdst[n * H + hd];
                v = v > 0.f ? v : 0.2f * v;
                s_alpha[t][hd] = expf(v - s_m[hd]) / s_den[hd];
            }
        }
        __syncthreads();
        if (act) {
            for (int k = 0; k < clen; k++) {
                float a = s_alpha[k][hd0];
                float4 hv = *(const float4*)(h + (size_t)s_src[k] * HC + c0);
                acc.x += a * hv.x; acc.y += a * hv.y;
                acc.z += a * hv.z; acc.w += a * hv.w;
            }
        }
    }

    // phase C: +bias, LayerNorm over HC, ELU
    float4 val = make_float4(0.f, 0.f, 0.f, 0.f);
    float sum = 0.f, sq = 0.f;
    if (act) {
        float4 b4 = *(const float4*)(bias + c0);
        val.x = acc.x + b4.x; val.y = acc.y + b4.y;
        val.z = acc.z + b4.z; val.w = acc.w + b4.w;
        sum = val.x + val.y + val.z + val.w;
        sq = val.x * val.x + val.y * val.y + val.z * val.z + val.w * val.w;
    }
    red[t] = sum; red[128 + t] = sq;
    __syncthreads();
    for (int o = 64; o; o >>= 1) {
        if (t < o) { red[t] += red[t + o]; red[128 + t] += red[128 + t + o]; }
        __syncthreads();
    }
    float mu = red[0] / HC;
    float var = red[128] / HC - mu * mu;
    float rstd = rsqrtf(var + LN_EPS);
    if (act) {
        float4 g4 = *(const float4*)(lng + c0);
        float4 o4 = *(const float4*)(lnb + c0);
        float y0 = (val.x - mu) * rstd * g4.x + o4.x;
        float y1 = (val.y - mu) * rstd * g4.y + o4.y;
        float y2 = (val.z - mu) * rstd * g4.z + o4.z;
        float y3 = (val.w - mu) * rstd * g4.w + o4.w;
        float4 r;
        r.x = y0 > 0.f ? y0 : expm1f(y0);
        r.y = y1 > 0.f ? y1 : expm1f(y1);
        r.z = y2 > 0.f ? y2 : expm1f(y2);
        r.w = y3 > 0.f ? y3 : expm1f(y3);
        *(float4*)(out + (size_t)n * HC + c0) = r;
    }
}

// ---------------- decoder epilogue: +bias -> LN -> ELU -----------------------
__global__ void ln_elu_k(const float* __restrict__ in, const float* __restrict__ bias,
                         const float* __restrict__ lng, const float* __restrict__ lnb,
                         float* __restrict__ out, int W) {
    __shared__ float sh[256];
    int n = blockIdx.x;
    int t = threadIdx.x;  // 128 threads
    float v[4];
    float sum = 0.f, sq = 0.f;
    int cnt = 0;
    for (int c = t; c < W; c += 128) {
        float val = in[(size_t)n * W + c] + bias[c];
        v[cnt++] = val; sum += val; sq += val * val;
    }
    sh[t] = sum; sh[128 + t] = sq;
    __syncthreads();
    for (int o = 64; o; o >>= 1) {
        if (t < o) { sh[t] += sh[t + o]; sh[128 + t] += sh[128 + t + o]; }
        __syncthreads();
    }
    float mu = sh[0] / W;
    float var = sh[128] / W - mu * mu;
    float rstd = rsqrtf(var + LN_EPS);
    cnt = 0;
    for (int c = t; c < W; c += 128) {
        float y = (v[cnt++] - mu) * rstd * lng[c] + lnb[c];
        out[(size_t)n * W + c] = y > 0.f ? y : expm1f(y);
    }
}

// ---------------- host orchestration -----------------------------------------
extern "C" void kernel_launch(void* const* d_in, const int* in_sizes, int n_in,
                              void* d_out, int out_size) {
    const float* x   = (const float*)d_in[0];
    const int*   ei  = (const int*)d_in[1];
    const float* W1  = (const float*)d_in[2];
    const float* a1s = (const float*)d_in[3];
    const float* a1d = (const float*)d_in[4];
    const float* b1  = (const float*)d_in[5];
    const float* g1  = (const float*)d_in[6];
    const float* bb1 = (const float*)d_in[7];
    const float* W2  = (const float*)d_in[8];
    const float* a2s = (const float*)d_in[9];
    const float* a2d = (const float*)d_in[10];
    const float* b2  = (const float*)d_in[11];
    const float* g2  = (const float*)d_in[12];
    const float* bb2 = (const float*)d_in[13];
    const float* W3  = (const float*)d_in[14];
    const float* a3s = (const float*)d_in[15];
    const float* a3d = (const float*)d_in[16];
    const float* b3  = (const float*)d_in[17];
    const float* g3  = (const float*)d_in[18];
    const float* bb3 = (const float*)d_in[19];
    const float* dW1   = (const float*)d_in[20];
    const float* db1   = (const float*)d_in[21];
    const float* lnd1g = (const float*)d_in[22];
    const float* lnd1b = (const float*)d_in[23];
    const float* dW2   = (const float*)d_in[24];
    const float* db2   = (const float*)d_in[25];
    const float* lnd2g = (const float*)d_in[26];
    const float* lnd2b = (const float*)d_in[27];

    float *h, *feat, *ssrc, *sdst;
    int *cnt, *off, *pos, *srcs;
    cudaGetSymbolAddress((void**)&h,    g_h);
    cudaGetSymbolAddress((void**)&feat, g_feat);
    cudaGetSymbolAddress((void**)&ssrc, g_ssrc);
    cudaGetSymbolAddress((void**)&sdst, g_sdst);
    cudaGetSymbolAddress((void**)&cnt,  g_cnt);
    cudaGetSymbolAddress((void**)&off,  g_off);
    cudaGetSymbolAddress((void**)&pos,  g_pos);
    cudaGetSymbolAddress((void**)&srcs, g_srcs);

    // ---- CSR build (graph shared across all layers) ----
    zero_k<<<(NN + 255) / 256, 256>>>(cnt, pos);
    hist_k<<<(EE + 255) / 256, 256>>>(ei, cnt);
    scan_k<<<1, 1024>>>(cnt, off);
    scatter_k<<<(ET + 255) / 256, 256>>>(ei, off, pos, srcs);

    const int MB = (NN + 127) / 128;

    // ---- one GAT layer ----
    auto gat = [&](const float* xin, int Fin, const float* W, const float* as_,
                   const float* ad_, const float* bias, const float* lg,
                   const float* lb, int H, int C, float* outf) {
        int HC = H * C;
        int shiftC = (C == 128) ? 7 : 6;
        gemm_tf32<<<dim3(HC / 64, MB), 256>>>(xin, W, h, NN, HC, Fin);
        scores_k<<<(NN * 32 + 255) / 256, 256>>>(h, as_, ad_, ssrc, sdst, H, C);
        gat_agg_k<<<NN, 128>>>(off, srcs, h, ssrc, sdst, bias, lg, lb, outf,
                               H, HC, shiftC);
    };

    gat(x,    128, W1, a1s, a1d, b1, g1, bb1, 4, 128, feat);
    gat(feat, 512, W2, a2s, a2d, b2, g2, bb2, 2, 128, feat);
    gat(feat, 256, W3, a3s, a3d, b3, g3, bb3, 1,  64, feat);

    // ---- decoder ----
    gemm_tf32<<<dim3(2, MB), 256>>>(feat, dW1, h, NN, 128, 64);
    ln_elu_k<<<NN, 128>>>(h, db1, lnd1g, lnd1b, feat, 128);
    gemm_tf32<<<dim3(2, MB), 256>>>(feat, dW2, h, NN, 128, 128);
    ln_elu_k<<<NN, 128>>>(h, db2, lnd2g, lnd2b, (float*)d_out, 128);
}

// round 5
// speedup vs baseline: 1.1746x; 1.1746x over previous
#include <cuda_runtime.h>
#include <math.h>
#include <stdint.h>

#define NN 50000
#define EE 400000
#define ET 450000      // EE + NN self loops
#define LN_EPS 1e-5f

// ---------------- scratch (device globals; allocation is forbidden) ----------
__device__ float g_h[(size_t)NN * 512];     // GEMM output per layer
__device__ float g_feat[(size_t)NN * 512];  // layer output / next input
__device__ float g_ssrc[NN * 4];
__device__ float g_sdst[NN * 4];
__device__ float g_alpha[(size_t)ET * 4];   // per-edge softmax weight
__device__ int   g_cnt[NN];
__device__ int   g_off[NN + 1];
__device__ int   g_pos[NN];
__device__ int   g_srcs[ET];

// ---------------- 3xTF32 tensor-core GEMM, cp.async double-buffered ----------
// C[M,N] = A[M,K] @ B[K,N], row-major fp32. Block 128x64, BK=16, 256 thr.
// Raw fp32 tiles in smem; hi/lo tf32 split at fragment read.
// acc += Ah*Bh + Ah*Bl + Al*Bh  (~fp32 accuracy).

__device__ __forceinline__ float f2tf32f(float x) {
    uint32_t r;
    asm("cvt.rna.tf32.f32 %0, %1;" : "=r"(r) : "f"(x));
    return __uint_as_float(r);
}

__device__ __forceinline__ void mma_tf32(float* c, const float* a, const float* b) {
    asm volatile(
        "mma.sync.aligned.m16n8k8.row.col.f32.tf32.tf32.f32 "
        "{%0,%1,%2,%3}, {%4,%5,%6,%7}, {%8,%9}, {%0,%1,%2,%3};"
        : "+f"(c[0]), "+f"(c[1]), "+f"(c[2]), "+f"(c[3])
        : "r"(__float_as_uint(a[0])), "r"(__float_as_uint(a[1])),
          "r"(__float_as_uint(a[2])), "r"(__float_as_uint(a[3])),
          "r"(__float_as_uint(b[0])), "r"(__float_as_uint(b[1])));
}

#define APAD 20   // 16 + 4: fragment reads conflict-free
#define BPAD 72   // 64 + 8

__global__ __launch_bounds__(256) void gemm_tf32(
        const float* __restrict__ A, const float* __restrict__ B,
        float* __restrict__ C, int M, int N, int K) {
    __shared__ float As[2][128][APAD];
    __shared__ float Bs[2][16][BPAD];

    int tid = threadIdx.x;
    int lane = tid & 31, wid = tid >> 5;
    int wm = (wid >> 1) * 32;
    int wn = (wid & 1) * 32;
    int q = lane & 3, t4 = lane >> 2;
    int row0 = blockIdx.y * 128, col0 = blockIdx.x * 64;

    // cp.async staging indices
    int a_r = tid >> 2, a_c = (tid & 3) << 2;        // + second half a_r+64
    int b_r = tid >> 4, b_n = (tid & 15) << 2;

    auto stage = [&](int buf, int k0) {
#pragma unroll
        for (int i = 0; i < 2; i++) {
            int r = a_r + i * 64;
            uint32_t dst = (uint32_t)__cvta_generic_to_shared(&As[buf][r][a_c]);
            const float* src = A + (size_t)(row0 + r) * K + k0 + a_c;
            int sz = (row0 + r < M) ? 16 : 0;
            asm volatile("cp.async.ca.shared.global [%0], [%1], 16, %2;"
                         :: "r"(dst), "l"(src), "r"(sz));
        }
        {
            uint32_t dst = (uint32_t)__cvta_generic_to_shared(&Bs[buf][b_r][b_n]);
            const float* src = B + (size_t)(k0 + b_r) * N + col0 + b_n;
            asm volatile("cp.async.ca.shared.global [%0], [%1], 16;"
                         :: "r"(dst), "l"(src));
        }
        asm volatile("cp.async.commit_group;");
    };

    float acc[2][4][4];
#pragma unroll
    for (int i = 0; i < 2; i++)
#pragma unroll
        for (int j = 0; j < 4; j++)
#pragma unroll
            for (int k = 0; k < 4; k++) acc[i][j][k] = 0.f;

    int ntiles = K >> 4;
    stage(0, 0);
    int buf = 0;
    for (int t = 0; t < ntiles; t++) {
        asm volatile("cp.async.wait_group 0;");
        __syncthreads();
        if (t + 1 < ntiles) stage(buf ^ 1, (t + 1) << 4);

#pragma unroll
        for (int kk = 0; kk < 16; kk += 8) {
            float ah[2][4], al[2][4], bh[4][2], bl[4][2];
#pragma unroll
            for (int mt = 0; mt < 2; mt++) {
                int m0 = wm + mt * 16 + t4;
                float a0 = As[buf][m0][kk + q];
                float a1 = As[buf][m0 + 8][kk + q];
                float a2 = As[buf][m0][kk + q + 4];
                float a3 = As[buf][m0 + 8][kk + q + 4];
                ah[mt][0] = f2tf32f(a0); al[mt][0] = f2tf32f(a0 - ah[mt][0]);
                ah[mt][1] = f2tf32f(a1); al[mt][1] = f2tf32f(a1 - ah[mt][1]);
                ah[mt][2] = f2tf32f(a2); al[mt][2] = f2tf32f(a2 - ah[mt][2]);
                ah[mt][3] = f2tf32f(a3); al[mt][3] = f2tf32f(a3 - ah[mt][3]);
            }
#pragma unroll
            for (int nt = 0; nt < 4; nt++) {
                int n0 = wn + nt * 8 + t4;
                float b0 = Bs[buf][kk + q][n0];
                float b1 = Bs[buf][kk + q + 4][n0];
                bh[nt][0] = f2tf32f(b0); bl[nt][0] = f2tf32f(b0 - bh[nt][0]);
                bh[nt][1] = f2tf32f(b1); bl[nt][1] = f2tf32f(b1 - bh[nt][1]);
            }
#pragma unroll
            for (int mt = 0; mt < 2; mt++)
#pragma unroll
                for (int nt = 0; nt < 4; nt++) {
                    mma_tf32(acc[mt][nt], ah[mt], bh[nt]);
                    mma_tf32(acc[mt][nt], ah[mt], bl[nt]);
                    mma_tf32(acc[mt][nt], al[mt], bh[nt]);
                }
        }
        buf ^= 1;
    }

#pragma unroll
    for (int mt = 0; mt < 2; mt++) {
        int r0 = row0 + wm + mt * 16 + t4;
#pragma unroll
        for (int nt = 0; nt < 4; nt++) {
            int cc = col0 + wn + nt * 8 + q * 2;
            if (r0 < M) {
                C[(size_t)r0 * N + cc]     = acc[mt][nt][0];
                C[(size_t)r0 * N + cc + 1] = acc[mt][nt][1];
            }
            if (r0 + 8 < M) {
                C[(size_t)(r0 + 8) * N + cc]     = acc[mt][nt][2];
                C[(size_t)(r0 + 8) * N + cc + 1] = acc[mt][nt][3];
            }
        }
    }
}

// ---------------- CSR construction -------------------------------------------
__global__ void zero_k(int* __restrict__ cnt, int* __restrict__ pos) {
    int i = blockIdx.x * blockDim.x + threadIdx.x;
    if (i < NN) { cnt[i] = 0; pos[i] = 0; }
}

__global__ void hist_k(const int* __restrict__ ei, int* __restrict__ cnt) {
    int e = blockIdx.x * blockDim.x + threadIdx.x;
    if (e < EE) atomicAdd(&cnt[ei[EE + e]], 1);
}

__global__ void scan_k(const int* __restrict__ cnt, int* __restrict__ off) {
    __shared__ int sh[1024];
    __shared__ int carry;
    int t = threadIdx.x;
    if (t == 0) carry = 0;
    __syncthreads();
    for (int base = 0; base < NN; base += 1024) {
        int i = base + t;
        int v = (i < NN) ? cnt[i] + 1 : 0;
        sh[t] = v;
        __syncthreads();
        for (int o = 1; o < 1024; o <<= 1) {
            int add = (t >= o) ? sh[t - o] : 0;
            __syncthreads();
            sh[t] += add;
            __syncthreads();
        }
        int total = sh[1023];
        if (i < NN) off[i + 1] = carry + sh[t];
        __syncthreads();
        if (t == 0) carry += total;
        __syncthreads();
    }
    if (t == 0) off[0] = 0;
}

__global__ void scatter_k(const int* __restrict__ ei, const int* __restrict__ off,
                          int* __restrict__ pos, int* __restrict__ srcs) {
    int e = blockIdx.x * blockDim.x + threadIdx.x;
    if (e >= ET) return;
    int s, d;
    if (e < EE) { s = ei[e]; d = ei[EE + e]; }
    else        { s = e - EE; d = s; }
    int p = atomicAdd(&pos[d], 1);
    srcs[off[d] + p] = s;
}

// ---------------- per-node attention scores: s = <h[n,h,:], a[h,:]> ----------
__global__ void scores_k(const float* __restrict__ h, const float* __restrict__ asrc,
                         const float* __restrict__ adst, float* __restrict__ ssrc,
                         float* __restrict__ sdst, int H, int C) {
    int warp = (blockIdx.x * blockDim.x + threadIdx.x) >> 5;
    int lane = threadIdx.x & 31;
    if (warp >= NN) return;
    int HC = H * C;
    for (int hd = 0; hd < H; hd++) {
        float ps = 0.f, pd = 0.f;
        for (int c = lane * 4; c < C; c += 128) {
            float4 hv = *(const float4*)(h + (size_t)warp * HC + hd * C + c);
            float4 as = *(const float4*)(asrc + hd * C + c);
            float4 ad = *(const float4*)(adst + hd * C + c);
            ps += hv.x * as.x + hv.y * as.y + hv.z * as.z + hv.w * as.w;
            pd += hv.x * ad.x + hv.y * ad.y + hv.z * ad.z + hv.w * ad.w;
        }
#pragma unroll
        for (int o = 16; o; o >>= 1) {
            ps += __shfl_down_sync(0xffffffffu, ps, o);
            pd += __shfl_down_sync(0xffffffffu, pd, o);
        }
        if (lane == 0) { ssrc[warp * H + hd] = ps; sdst[warp * H + hd] = pd; }
    }
}

// ---------------- alpha: warp per dst node, softmax over incoming edges ------
__global__ void alpha_k(const int* __restrict__ off, const int* __restrict__ srcs,
                        const float* __restrict__ ssrc, const float* __restrict__ sdst,
                        float* __restrict__ alpha, int H) {
    int n = (blockIdx.x * blockDim.x + threadIdx.x) >> 5;
    int lane = threadIdx.x & 31;
    if (n >= NN) return;
    int beg = off[n], end = off[n + 1];
    float sdn[4];
    for (int hd = 0; hd < H; hd++) sdn[hd] = sdst[n * H + hd];

    float mx[4] = {-INFINITY, -INFINITY, -INFINITY, -INFINITY};
    for (int j = beg + lane; j < end; j += 32) {
        int s = srcs[j];
        for (int hd = 0; hd < H; hd++) {
            float v = ssrc[s * H + hd] + sdn[hd];
            v = v > 0.f ? v : 0.2f * v;
            mx[hd] = fmaxf(mx[hd], v);
        }
    }
#pragma unroll
    for (int o = 16; o; o >>= 1)
        for (int hd = 0; hd < H; hd++)
            mx[hd] = fmaxf(mx[hd], __shfl_xor_sync(0xffffffffu, mx[hd], o));

    float dn[4] = {0.f, 0.f, 0.f, 0.f};
    for (int j = beg + lane; j < end; j += 32) {
        int s = srcs[j];
        for (int hd = 0; hd < H; hd++) {
            float v = ssrc[s * H + hd] + sdn[hd];
            v = v > 0.f ? v : 0.2f * v;
            float e = expf(v - mx[hd]);
            alpha[(size_t)j * H + hd] = e;
            dn[hd] += e;
        }
    }
#pragma unroll
    for (int o = 16; o; o >>= 1)
        for (int hd = 0; hd < H; hd++)
            dn[hd] += __shfl_xor_sync(0xffffffffu, dn[hd], o);
    float inv[4];
    for (int hd = 0; hd < H; hd++) inv[hd] = 1.f / dn[hd];
    for (int j = beg + lane; j < end; j += 32)
        for (int hd = 0; hd < H; hd++)
            alpha[(size_t)j * H + hd] *= inv[hd];
}

// ---------------- fused gather-aggregate + bias + LN + ELU -------------------
#define CHUNK 64
__global__ __launch_bounds__(128) void gat_agg_k(
        const int* __restrict__ off, const int* __restrict__ srcs,
        const float* __restrict__ alpha, const float* __restrict__ h,
        const float* __restrict__ bias, const float* __restrict__ lng,
        const float* __restrict__ lnb, float* __restrict__ out,
        int H, int HC, int shiftC) {
    __shared__ float s_alpha[CHUNK][4];
    __shared__ int   s_src[CHUNK];
    __shared__ float red[256];

    int n = blockIdx.x;
    int t = threadIdx.x;
    int beg = off[n], end = off[n + 1];

    int c0 = t * 4;
    bool act = c0 < HC;
    int hd0 = act ? (c0 >> shiftC) : 0;
    float4 acc = make_float4(0.f, 0.f, 0.f, 0.f);

    for (int cb = beg; cb < end; cb += CHUNK) {
        int clen = min(CHUNK, end - cb);
        __syncthreads();
        if (t < clen) {
            s_src[t] = srcs[cb + t];
            for (int hd = 0; hd < H; hd++)
                s_alpha[t][hd] = alpha[(size_t)(cb + t) * H + hd];
        }
        __syncthreads();
        if (act) {
            for (int k = 0; k < clen; k++) {
                float a = s_alpha[k][hd0];
                float4 hv = *(const float4*)(h + (size_t)s_src[k] * HC + c0);
                acc.x += a * hv.x; acc.y += a * hv.y;
                acc.z += a * hv.z; acc.w += a * hv.w;
            }
        }
    }

    float4 val = make_float4(0.f, 0.f, 0.f, 0.f);
    float sum = 0.f, sq = 0.f;
    if (act) {
        float4 b4 = *(const float4*)(bias + c0);
        val.x = acc.x + b4.x; val.y = acc.y + b4.y;
        val.z = acc.z + b4.z; val.w = acc.w + b4.w;
        sum = val.x + val.y + val.z + val.w;
        sq = val.x * val.x + val.y * val.y + val.z * val.z + val.w * val.w;
    }
    red[t] = sum; red[128 + t] = sq;
    __syncthreads();
    for (int o = 64; o; o >>= 1) {
        if (t < o) { red[t] += red[t + o]; red[128 + t] += red[128 + t + o]; }
        __syncthreads();
    }
    float mu = red[0] / HC;
    float var = red[128] / HC - mu * mu;
    float rstd = rsqrtf(var + LN_EPS);
    if (act) {
        float4 g4 = *(const float4*)(lng + c0);
        float4 o4 = *(const float4*)(lnb + c0);
        float y0 = (val.x - mu) * rstd * g4.x + o4.x;
        float y1 = (val.y - mu) * rstd * g4.y + o4.y;
        float y2 = (val.z - mu) * rstd * g4.z + o4.z;
        float y3 = (val.w - mu) * rstd * g4.w + o4.w;
        float4 r;
        r.x = y0 > 0.f ? y0 : expm1f(y0);
        r.y = y1 > 0.f ? y1 : expm1f(y1);
        r.z = y2 > 0.f ? y2 : expm1f(y2);
        r.w = y3 > 0.f ? y3 : expm1f(y3);
        *(float4*)(out + (size_t)n * HC + c0) = r;
    }
}

// ---------------- decoder epilogue: +bias -> LN -> ELU -----------------------
__global__ void ln_elu_k(const float* __restrict__ in, const float* __restrict__ bias,
                         const float* __restrict__ lng, const float* __restrict__ lnb,
                         float* __restrict__ out, int W) {
    __shared__ float sh[256];
    int n = blockIdx.x;
    int t = threadIdx.x;  // 128 threads
    float v[4];
    float sum = 0.f, sq = 0.f;
    int cnt = 0;
    for (int c = t; c < W; c += 128) {
        float val = in[(size_t)n * W + c] + bias[c];
        v[cnt++] = val; sum += val; sq += val * val;
    }
    sh[t] = sum; sh[128 + t] = sq;
    __syncthreads();
    for (int o = 64; o; o >>= 1) {
        if (t < o) { sh[t] += sh[t + o]; sh[128 + t] += sh[128 + t + o]; }
        __syncthreads();
    }
    float mu = sh[0] / W;
    float var = sh[128] / W - mu * mu;
    float rstd = rsqrtf(var + LN_EPS);
    cnt = 0;
    for (int c = t; c < W; c += 128) {
        float y = (v[cnt++] - mu) * rstd * lng[c] + lnb[c];
        out[(size_t)n * W + c] = y > 0.f ? y : expm1f(y);
    }
}

// ---------------- host orchestration -----------------------------------------
extern "C" void kernel_launch(void* const* d_in, const int* in_sizes, int n_in,
                              void* d_out, int out_size) {
    const float* x   = (const float*)d_in[0];
    const int*   ei  = (const int*)d_in[1];
    const float* W1  = (const float*)d_in[2];
    const float* a1s = (const float*)d_in[3];
    const float* a1d = (const float*)d_in[4];
    const float* b1  = (const float*)d_in[5];
    const float* g1  = (const float*)d_in[6];
    const float* bb1 = (const float*)d_in[7];
    const float* W2  = (const float*)d_in[8];
    const float* a2s = (const float*)d_in[9];
    const float* a2d = (const float*)d_in[10];
    const float* b2  = (const float*)d_in[11];
    const float* g2  = (const float*)d_in[12];
    const float* bb2 = (const float*)d_in[13];
    const float* W3  = (const float*)d_in[14];
    const float* a3s = (const float*)d_in[15];
    const float* a3d = (const float*)d_in[16];
    const float* b3  = (const float*)d_in[17];
    const float* g3  = (const float*)d_in[18];
    const float* bb3 = (const float*)d_in[19];
    const float* dW1   = (const float*)d_in[20];
    const float* db1   = (const float*)d_in[21];
    const float* lnd1g = (const float*)d_in[22];
    const float* lnd1b = (const float*)d_in[23];
    const float* dW2   = (const float*)d_in[24];
    const float* db2   = (const float*)d_in[25];
    const float* lnd2g = (const float*)d_in[26];
    const float* lnd2b = (const float*)d_in[27];

    float *h, *feat, *ssrc, *sdst, *alpha;
    int *cnt, *off, *pos, *srcs;
    cudaGetSymbolAddress((void**)&h,     g_h);
    cudaGetSymbolAddress((void**)&feat,  g_feat);
    cudaGetSymbolAddress((void**)&ssrc,  g_ssrc);
    cudaGetSymbolAddress((void**)&sdst,  g_sdst);
    cudaGetSymbolAddress((void**)&alpha, g_alpha);
    cudaGetSymbolAddress((void**)&cnt,   g_cnt);
    cudaGetSymbolAddress((void**)&off,   g_off);
    cudaGetSymbolAddress((void**)&pos,   g_pos);
    cudaGetSymbolAddress((void**)&srcs,  g_srcs);

    // ---- CSR build (graph shared across all layers) ----
    zero_k<<<(NN + 255) / 256, 256>>>(cnt, pos);
    hist_k<<<(EE + 255) / 256, 256>>>(ei, cnt);
    scan_k<<<1, 1024>>>(cnt, off);
    scatter_k<<<(ET + 255) / 256, 256>>>(ei, off, pos, srcs);

    const int MB = (NN + 127) / 128;

    // ---- one GAT layer ----
    auto gat = [&](const float* xin, int Fin, const float* W, const float* as_,
                   const float* ad_, const float* bias, const float* lg,
                   const float* lb, int H, int C, float* outf) {
        int HC = H * C;
        int shiftC = (C == 128) ? 7 : 6;
        gemm_tf32<<<dim3(HC / 64, MB), 256>>>(xin, W, h, NN, HC, Fin);
        scores_k<<<(NN * 32 + 255) / 256, 256>>>(h, as_, ad_, ssrc, sdst, H, C);
        alpha_k<<<(NN * 32 + 255) / 256, 256>>>(off, srcs, ssrc, sdst, alpha, H);
        gat_agg_k<<<NN, 128>>>(off, srcs, alpha, h, bias, lg, lb, outf,
                               H, HC, shiftC);
    };

    gat(x,    128, W1, a1s, a1d, b1, g1, bb1, 4, 128, feat);
    gat(feat, 512, W2, a2s, a2d, b2, g2, bb2, 2, 128, feat);
    gat(feat, 256, W3, a3s, a3d, b3, g3, bb3, 1,  64, feat);

    // ---- decoder ----
    gemm_tf32<<<dim3(2, MB), 256>>>(feat, dW1, h, NN, 128, 64);
    ln_elu_k<<<NN, 128>>>(h, db1, lnd1g, lnd1b, feat, 128);
    gemm_tf32<<<dim3(2, MB), 256>>>(feat, dW2, h, NN, 128, 128);
    ln_elu_k<<<NN, 128>>>(h, db2, lnd2g, lnd2b, (float*)d_out, 128);
}

// round 6
// speedup vs baseline: 1.4202x; 1.2091x over previous
#include <cuda_runtime.h>
#include <cuda_bf16.h>
#include <math.h>
#include <stdint.h>

#define NN 50000
#define EE 400000
#define ET 450000      // EE + NN self loops
#define LN_EPS 1e-5f

// ---------------- scratch (device globals; allocation is forbidden) ----------
__device__ float g_h[(size_t)NN * 512];     // GEMM output per layer
__device__ float g_feat[(size_t)NN * 512];  // layer output / next input
__device__ float g_ssrc[NN * 4];
__device__ float g_sdst[NN * 4];
__device__ float g_alpha[(size_t)ET * 4];   // per-edge softmax weight
__device__ int   g_cnt[NN];
__device__ int   g_off[NN + 1];
__device__ int   g_pos[NN];
__device__ int   g_srcs[ET];

// ---------------- bf16x3 tensor-core GEMM ------------------------------------
// C[M,N] = A[M,K] @ B[K,N], row-major fp32. Block 128x64, BK=16, 256 threads.
// fp32 split into bf16 hi+lo at staging (packed bf16x2 along k in smem).
// acc += Ah*Bh + Ah*Bl + Al*Bh via mma.m16n8k16 (~1e-5 rel accuracy).
// Requires N % 64 == 0, K % 16 == 0.

__device__ __forceinline__ uint32_t pack_hi(float x, float y, float& lx, float& ly) {
    __nv_bfloat16 hx = __float2bfloat16_rn(x);
    __nv_bfloat16 hy = __float2bfloat16_rn(y);
    lx = x - __bfloat162float(hx);
    ly = y - __bfloat162float(hy);
    __nv_bfloat162 p = __halves2bfloat162(hx, hy);   // x in low bits (k even first)
    return *(uint32_t*)&p;
}
__device__ __forceinline__ uint32_t pack_lo(float lx, float ly) {
    __nv_bfloat162 p = __halves2bfloat162(__float2bfloat16_rn(lx),
                                          __float2bfloat16_rn(ly));
    return *(uint32_t*)&p;
}

__device__ __forceinline__ void mma_bf16(float* c, const uint32_t* a, const uint32_t* b) {
    asm volatile(
        "mma.sync.aligned.m16n8k16.row.col.f32.bf16.bf16.f32 "
        "{%0,%1,%2,%3}, {%4,%5,%6,%7}, {%8,%9}, {%0,%1,%2,%3};"
        : "+f"(c[0]), "+f"(c[1]), "+f"(c[2]), "+f"(c[3])
        : "r"(a[0]), "r"(a[1]), "r"(a[2]), "r"(a[3]), "r"(b[0]), "r"(b[1]));
}

__global__ __launch_bounds__(256) void gemm_bf16x3(
        const float* __restrict__ A, const float* __restrict__ B,
        float* __restrict__ C, int M, int N, int K) {
    // [k2][m] / [k2][n] packed bf16x2; pads 136/72 (mod 32 == 8) -> conflict-free
    __shared__ uint32_t Ahi[2][8][136], Alo[2][8][136];
    __shared__ uint32_t Bhi[2][8][72],  Blo[2][8][72];

    int tid = threadIdx.x;
    int lane = tid & 31, wid = tid >> 5;
    int wm = (wid >> 1) * 32;
    int wn = (wid & 1) * 32;
    int q = lane & 3, t4 = lane >> 2;
    int row0 = blockIdx.y * 128, col0 = blockIdx.x * 64;

    // staging indices
    int a_r = tid >> 2, a_k2 = (tid & 3) * 2;        // A: rows a_r, a_r+64; k cols a_k2*2..+3
    int b_k2 = tid >> 5, b_n = (lane) * 2;           // B: k rows 2*b_k2, 2*b_k2+1; cols b_n, b_n+1

    float4 pa[2];                                    // prefetch regs
    float2 pb0, pb1;

    auto prefetch = [&](int k0) {
#pragma unroll
        for (int i = 0; i < 2; i++) {
            int r = row0 + a_r + i * 64;
            if (r < M) pa[i] = *(const float4*)(A + (size_t)r * K + k0 + a_k2 * 2);
            else       pa[i] = make_float4(0.f, 0.f, 0.f, 0.f);
        }
        const float* bp = B + (size_t)(k0 + b_k2 * 2) * N + col0 + b_n;
        pb0 = *(const float2*)bp;
        pb1 = *(const float2*)(bp + N);
    };

    auto convert_store = [&](int buf) {
#pragma unroll
        for (int i = 0; i < 2; i++) {
            int r = a_r + i * 64;
            float lx, ly, lz, lw;
            uint32_t h0 = pack_hi(pa[i].x, pa[i].y, lx, ly);
            uint32_t h1 = pack_hi(pa[i].z, pa[i].w, lz, lw);
            Ahi[buf][a_k2][r]     = h0;
            Ahi[buf][a_k2 + 1][r] = h1;
            Alo[buf][a_k2][r]     = pack_lo(lx, ly);
            Alo[buf][a_k2 + 1][r] = pack_lo(lz, lw);
        }
        {
            float l00, l10, l01, l11;
            uint32_t h0 = pack_hi(pb0.x, pb1.x, l00, l10);  // col b_n: (k even, k odd)
            uint32_t h1 = pack_hi(pb0.y, pb1.y, l01, l11);  // col b_n+1
            Bhi[buf][b_k2][b_n]     = h0;
            Bhi[buf][b_k2][b_n + 1] = h1;
            Blo[buf][b_k2][b_n]     = pack_lo(l00, l10);
            Blo[buf][b_k2][b_n + 1] = pack_lo(l01, l11);
        }
    };

    float acc[2][4][4];
#pragma unroll
    for (int i = 0; i < 2; i++)
#pragma unroll
        for (int j = 0; j < 4; j++)
#pragma unroll
            for (int k = 0; k < 4; k++) acc[i][j][k] = 0.f;

    int ntiles = K >> 4;
    prefetch(0);
    convert_store(0);
    __syncthreads();

    int buf = 0;
    for (int t = 0; t < ntiles; t++) {
        if (t + 1 < ntiles) prefetch((t + 1) << 4);

        // fragments
        uint32_t ah[2][4], al[2][4], bh[4][2], bl[4][2];
#pragma unroll
        for (int mt = 0; mt < 2; mt++) {
            int m0 = wm + mt * 16 + t4;
            ah[mt][0] = Ahi[buf][q][m0];     ah[mt][1] = Ahi[buf][q][m0 + 8];
            ah[mt][2] = Ahi[buf][q + 4][m0]; ah[mt][3] = Ahi[buf][q + 4][m0 + 8];
            al[mt][0] = Alo[buf][q][m0];     al[mt][1] = Alo[buf][q][m0 + 8];
            al[mt][2] = Alo[buf][q + 4][m0]; al[mt][3] = Alo[buf][q + 4][m0 + 8];
        }
#pragma unroll
        for (int nt = 0; nt < 4; nt++) {
            int n0 = wn + nt * 8 + t4;
            bh[nt][0] = Bhi[buf][q][n0]; bh[nt][1] = Bhi[buf][q + 4][n0];
            bl[nt][0] = Blo[buf][q][n0]; bl[nt][1] = Blo[buf][q + 4][n0];
        }
#pragma unroll
        for (int mt = 0; mt < 2; mt++)
#pragma unroll
            for (int nt = 0; nt < 4; nt++) {
                mma_bf16(acc[mt][nt], ah[mt], bh[nt]);
                mma_bf16(acc[mt][nt], ah[mt], bl[nt]);
                mma_bf16(acc[mt][nt], al[mt], bh[nt]);
            }

        if (t + 1 < ntiles) convert_store(buf ^ 1);
        __syncthreads();
        buf ^= 1;
    }

#pragma unroll
    for (int mt = 0; mt < 2; mt++) {
        int r0 = row0 + wm + mt * 16 + t4;
#pragma unroll
        for (int nt = 0; nt < 4; nt++) {
            int cc = col0 + wn + nt * 8 + q * 2;
            if (r0 < M) {
                C[(size_t)r0 * N + cc]     = acc[mt][nt][0];
                C[(size_t)r0 * N + cc + 1] = acc[mt][nt][1];
            }
            if (r0 + 8 < M) {
                C[(size_t)(r0 + 8) * N + cc]     = acc[mt][nt][2];
                C[(size_t)(r0 + 8) * N + cc + 1] = acc[mt][nt][3];
            }
        }
    }
}

// ---------------- CSR construction -------------------------------------------
__global__ void zero_k(int* __restrict__ cnt, int* __restrict__ pos) {
    int i = blockIdx.x * blockDim.x + threadIdx.x;
    if (i < NN) { cnt[i] = 0; pos[i] = 0; }
}

__global__ void hist_k(const int* __restrict__ ei, int* __restrict__ cnt) {
    int e = blockIdx.x * blockDim.x + threadIdx.x;
    if (e < EE) atomicAdd(&cnt[ei[EE + e]], 1);
}

// single-block scan of (cnt[i]+1) -> off[i+1]; off[0]=0  (shfl warp scan)
__global__ void scan_k(const int* __restrict__ cnt, int* __restrict__ off) {
    __shared__ int wsum[32];
    __shared__ int carry_s;
    int t = threadIdx.x, lane = t & 31, w = t >> 5;
    if (t == 0) carry_s = 0;
    __syncthreads();
    for (int base = 0; base < NN; base += 1024) {
        int i = base + t;
        int x = (i < NN) ? cnt[i] + 1 : 0;
#pragma unroll
        for (int o = 1; o < 32; o <<= 1) {
            int y = __shfl_up_sync(0xffffffffu, x, o);
            if (lane >= o) x += y;
        }
        if (lane == 31) wsum[w] = x;
        __syncthreads();
        if (w == 0) {
            int s = wsum[lane];
#pragma unroll
            for (int o = 1; o < 32; o <<= 1) {
                int y = __shfl_up_sync(0xffffffffu, s, o);
                if (lane >= o) s += y;
            }
            wsum[lane] = s;
        }
        __syncthreads();
        int woff = (w == 0) ? 0 : wsum[w - 1];
        int total = wsum[31];
        if (i < NN) off[i + 1] = carry_s + woff + x;
        __syncthreads();
        if (t == 0) carry_s += total;
        __syncthreads();
    }
    if (threadIdx.x == 0) off[0] = 0;
}

__global__ void scatter_k(const int* __restrict__ ei, const int* __restrict__ off,
                          int* __restrict__ pos, int* __restrict__ srcs) {
    int e = blockIdx.x * blockDim.x + threadIdx.x;
    if (e >= ET) return;
    int s, d;
    if (e < EE) { s = ei[e]; d = ei[EE + e]; }
    else        { s = e - EE; d = s; }
    int p = atomicAdd(&pos[d], 1);
    srcs[off[d] + p] = s;
}

// ---------------- per-node attention scores: s = <h[n,h,:], a[h,:]> ----------
__global__ void scores_k(const float* __restrict__ h, const float* __restrict__ asrc,
                         const float* __restrict__ adst, float* __restrict__ ssrc,
                         float* __restrict__ sdst, int H, int C) {
    int warp = (blockIdx.x * blockDim.x + threadIdx.x) >> 5;
    int lane = threadIdx.x & 31;
    if (warp >= NN) return;
    int HC = H * C;
    for (int hd = 0; hd < H; hd++) {
        float ps = 0.f, pd = 0.f;
        for (int c = lane * 4; c < C; c += 128) {
            float4 hv = *(const float4*)(h + (size_t)warp * HC + hd * C + c);
            float4 as = *(const float4*)(asrc + hd * C + c);
            float4 ad = *(const float4*)(adst + hd * C + c);
            ps += hv.x * as.x + hv.y * as.y + hv.z * as.z + hv.w * as.w;
            pd += hv.x * ad.x + hv.y * ad.y + hv.z * ad.z + hv.w * ad.w;
        }
#pragma unroll
        for (int o = 16; o; o >>= 1) {
            ps += __shfl_down_sync(0xffffffffu, ps, o);
            pd += __shfl_down_sync(0xffffffffu, pd, o);
        }
        if (lane == 0) { ssrc[warp * H + hd] = ps; sdst[warp * H + hd] = pd; }
    }
}

// ---------------- alpha: warp per dst node, softmax over incoming edges ------
__global__ void alpha_k(const int* __restrict__ off, const int* __restrict__ srcs,
                        const float* __restrict__ ssrc, const float* __restrict__ sdst,
                        float* __restrict__ alpha, int H) {
    int n = (blockIdx.x * blockDim.x + threadIdx.x) >> 5;
    int lane = threadIdx.x & 31;
    if (n >= NN) return;
    int beg = off[n], end = off[n + 1];
    float sdn[4];
    for (int hd = 0; hd < H; hd++) sdn[hd] = sdst[n * H + hd];

    float mx[4] = {-INFINITY, -INFINITY, -INFINITY, -INFINITY};
    for (int j = beg + lane; j < end; j += 32) {
        int s = srcs[j];
        for (int hd = 0; hd < H; hd++) {
            float v = ssrc[s * H + hd] + sdn[hd];
            v = v > 0.f ? v : 0.2f * v;
            mx[hd] = fmaxf(mx[hd], v);
        }
    }
#pragma unroll
    for (int o = 16; o; o >>= 1)
        for (int hd = 0; hd < H; hd++)
            mx[hd] = fmaxf(mx[hd], __shfl_xor_sync(0xffffffffu, mx[hd], o));

    float dn[4] = {0.f, 0.f, 0.f, 0.f};
    for (int j = beg + lane; j < end; j += 32) {
        int s = srcs[j];
        for (int hd = 0; hd < H; hd++) {
            float v = ssrc[s * H + hd] + sdn[hd];
            v = v > 0.f ? v : 0.2f * v;
            float e = expf(v - mx[hd]);
            alpha[(size_t)j * H + hd] = e;
            dn[hd] += e;
        }
    }
#pragma unroll
    for (int o = 16; o; o >>= 1)
        for (int hd = 0; hd < H; hd++)
            dn[hd] += __shfl_xor_sync(0xffffffffu, dn[hd], o);
    float inv[4];
    for (int hd = 0; hd < H; hd++) inv[hd] = 1.f / dn[hd];
    for (int j = beg + lane; j < end; j += 32)
        for (int hd = 0; hd < H; hd++)
            alpha[(size_t)j * H + hd] *= inv[hd];
}

// ---------------- fused gather-aggregate + bias + LN + ELU -------------------
#define CHUNK 64
__global__ __launch_bounds__(128) void gat_agg_k(
        const int* __restrict__ off, const int* __restrict__ srcs,
        const float* __restrict__ alpha, const float* __restrict__ h,
        const float* __restrict__ bias, const float* __restrict__ lng,
        const float* __restrict__ lnb, float* __restrict__ out,
        int H, int HC, int shiftC) {
    __shared__ float s_alpha[CHUNK][4];
    __shared__ int   s_src[CHUNK];
    __shared__ float red[256];

    int n = blockIdx.x;
    int t = threadIdx.x;
    int beg = off[n], end = off[n + 1];

    int c0 = t * 4;
    bool act = c0 < HC;
    int hd0 = act ? (c0 >> shiftC) : 0;
    float4 acc = make_float4(0.f, 0.f, 0.f, 0.f);

    for (int cb = beg; cb < end; cb += CHUNK) {
        int clen = min(CHUNK, end - cb);
        __syncthreads();
        if (t < clen) {
            s_src[t] = srcs[cb + t];
            for (int hd = 0; hd < H; hd++)
                s_alpha[t][hd] = alpha[(size_t)(cb + t) * H + hd];
        }
        __syncthreads();
        if (act) {
            for (int k = 0; k < clen; k++) {
                float a = s_alpha[k][hd0];
                float4 hv = *(const float4*)(h + (size_t)s_src[k] * HC + c0);
                acc.x += a * hv.x; acc.y += a * hv.y;
                acc.z += a * hv.z; acc.w += a * hv.w;
            }
        }
    }

    float4 val = make_float4(0.f, 0.f, 0.f, 0.f);
    float sum = 0.f, sq = 0.f;
    if (act) {
        float4 b4 = *(const float4*)(bias + c0);
        val.x = acc.x + b4.x; val.y = acc.y + b4.y;
        val.z = acc.z + b4.z; val.w = acc.w + b4.w;
        sum = val.x + val.y + val.z + val.w;
        sq = val.x * val.x + val.y * val.y + val.z * val.z + val.w * val.w;
    }
    red[t] = sum; red[128 + t] = sq;
    __syncthreads();
    for (int o = 64; o; o >>= 1) {
        if (t < o) { red[t] += red[t + o]; red[128 + t] += red[128 + t + o]; }
        __syncthreads();
    }
    float mu = red[0] / HC;
    float var = red[128] / HC - mu * mu;
    float rstd = rsqrtf(var + LN_EPS);
    if (act) {
        float4 g4 = *(const float4*)(lng + c0);
        float4 o4 = *(const float4*)(lnb + c0);
        float y0 = (val.x - mu) * rstd * g4.x + o4.x;
        float y1 = (val.y - mu) * rstd * g4.y + o4.y;
        float y2 = (val.z - mu) * rstd * g4.z + o4.z;
        float y3 = (val.w - mu) * rstd * g4.w + o4.w;
        float4 r;
        r.x = y0 > 0.f ? y0 : expm1f(y0);
        r.y = y1 > 0.f ? y1 : expm1f(y1);
        r.z = y2 > 0.f ? y2 : expm1f(y2);
        r.w = y3 > 0.f ? y3 : expm1f(y3);
        *(float4*)(out + (size_t)n * HC + c0) = r;
    }
}

// ---------------- decoder epilogue: +bias -> LN -> ELU -----------------------
__global__ void ln_elu_k(const float* __restrict__ in, const float* __restrict__ bias,
                         const float* __restrict__ lng, const float* __restrict__ lnb,
                         float* __restrict__ out, int W) {
    __shared__ float sh[256];
    int n = blockIdx.x;
    int t = threadIdx.x;  // 128 threads
    float v[4];
    float sum = 0.f, sq = 0.f;
    int cnt = 0;
    for (int c = t; c < W; c += 128) {
        float val = in[(size_t)n * W + c] + bias[c];
        v[cnt++] = val; sum += val; sq += val * val;
    }
    sh[t] = sum; sh[128 + t] = sq;
    __syncthreads();
    for (int o = 64; o; o >>= 1) {
        if (t < o) { sh[t] += sh[t + o]; sh[128 + t] += sh[128 + t + o]; }
        __syncthreads();
    }
    float mu = sh[0] / W;
    float var = sh[128] / W - mu * mu;
    float rstd = rsqrtf(var + LN_EPS);
    cnt = 0;
    for (int c = t; c < W; c += 128) {
        float y = (v[cnt++] - mu) * rstd * lng[c] + lnb[c];
        out[(size_t)n * W + c] = y > 0.f ? y : expm1f(y);
    }
}

// ---------------- host orchestration -----------------------------------------
extern "C" void kernel_launch(void* const* d_in, const int* in_sizes, int n_in,
                              void* d_out, int out_size) {
    const float* x   = (const float*)d_in[0];
    const int*   ei  = (const int*)d_in[1];
    const float* W1  = (const float*)d_in[2];
    const float* a1s = (const float*)d_in[3];
    const float* a1d = (const float*)d_in[4];
    const float* b1  = (const float*)d_in[5];
    const float* g1  = (const float*)d_in[6];
    const float* bb1 = (const float*)d_in[7];
    const float* W2  = (const float*)d_in[8];
    const float* a2s = (const float*)d_in[9];
    const float* a2d = (const float*)d_in[10];
    const float* b2  = (const float*)d_in[11];
    const float* g2  = (const float*)d_in[12];
    const float* bb2 = (const float*)d_in[13];
    const float* W3  = (const float*)d_in[14];
    const float* a3s = (const float*)d_in[15];
    const float* a3d = (const float*)d_in[16];
    const float* b3  = (const float*)d_in[17];
    const float* g3  = (const float*)d_in[18];
    const float* bb3 = (const float*)d_in[19];
    const float* dW1   = (const float*)d_in[20];
    const float* db1   = (const float*)d_in[21];
    const float* lnd1g = (const float*)d_in[22];
    const float* lnd1b = (const float*)d_in[23];
    const float* dW2   = (const float*)d_in[24];
    const float* db2   = (const float*)d_in[25];
    const float* lnd2g = (const float*)d_in[26];
    const float* lnd2b = (const float*)d_in[27];

    float *h, *feat, *ssrc, *sdst, *alpha;
    int *cnt, *off, *pos, *srcs;
    cudaGetSymbolAddress((void**)&h,     g_h);
    cudaGetSymbolAddress((void**)&feat,  g_feat);
    cudaGetSymbolAddress((void**)&ssrc,  g_ssrc);
    cudaGetSymbolAddress((void**)&sdst,  g_sdst);
    cudaGetSymbolAddress((void**)&alpha, g_alpha);
    cudaGetSymbolAddress((void**)&cnt,   g_cnt);
    cudaGetSymbolAddress((void**)&off,   g_off);
    cudaGetSymbolAddress((void**)&pos,   g_pos);
    cudaGetSymbolAddress((void**)&srcs,  g_srcs);

    // ---- CSR build (graph shared across all layers) ----
    zero_k<<<(NN + 255) / 256, 256>>>(cnt, pos);
    hist_k<<<(EE + 255) / 256, 256>>>(ei, cnt);
    scan_k<<<1, 1024>>>(cnt, off);
    scatter_k<<<(ET + 255) / 256, 256>>>(ei, off, pos, srcs);

    const int MB = (NN + 127) / 128;

    // ---- one GAT layer ----
    auto gat = [&](const float* xin, int Fin, const float* W, const float* as_,
                   const float* ad_, const float* bias, const float* lg,
                   const float* lb, int H, int C, float* outf) {
        int HC = H * C;
        int shiftC = (C == 128) ? 7 : 6;
        gemm_bf16x3<<<dim3(HC / 64, MB), 256>>>(xin, W, h, NN, HC, Fin);
        scores_k<<<(NN * 32 + 255) / 256, 256>>>(h, as_, ad_, ssrc, sdst, H, C);
        alpha_k<<<(NN * 32 + 255) / 256, 256>>>(off, srcs, ssrc, sdst, alpha, H);
        gat_agg_k<<<NN, 128>>>(off, srcs, alpha, h, bias, lg, lb, outf,
                               H, HC, shiftC);
    };

    gat(x,    128, W1, a1s, a1d, b1, g1, bb1, 4, 128, feat);
    gat(feat, 512, W2, a2s, a2d, b2, g2, bb2, 2, 128, feat);
    gat(feat, 256, W3, a3s, a3d, b3, g3, bb3, 1,  64, feat);

    // ---- decoder ----
    gemm_bf16x3<<<dim3(2, MB), 256>>>(feat, dW1, h, NN, 128, 64);
    ln_elu_k<<<NN, 128>>>(h, db1, lnd1g, lnd1b, feat, 128);
    gemm_bf16x3<<<dim3(2, MB), 256>>>(feat, dW2, h, NN, 128, 128);
    ln_elu_k<<<NN, 128>>>(h, db2, lnd2g, lnd2b, (float*)d_out, 128);
}